// round 1
// baseline (speedup 1.0000x reference)
#include <cuda_runtime.h>

#define Bq  2
#define Sq  2048
#define Dq  1024
#define Hq  16
#define DKV 64

// ---------------- scratch (static device allocations; no cudaMalloc) --------
__device__ float g_Q[Bq * Hq * Sq * DKV];      // 16 MB  [b,h,s,dkv]
__device__ float g_K[Bq * Hq * Sq * DKV];      // 16 MB
__device__ float g_V[Bq * Hq * Sq * DKV];      // 16 MB
__device__ float g_ctx[Bq * Sq * Dq];          // 16 MB  [b,s,d]
__device__ float g_rowsum[Bq * Hq * Sq];       // 256 KB
__device__ float g_bias[Hq * 4096];            // 256 KB [h][delta], delta = k-q+2048

// ---------------- fast exp in the FMA pipe (avoids MUFU bottleneck) ---------
__device__ __forceinline__ float fexp(float x) {
    float t = x * 1.4426950408889634f;           // x * log2(e)
    t = fmaxf(t, -126.0f);                       // -1e9 masked scores -> ~0
    float nf = floorf(t);
    float u = (t - nf) * 0.6931471805599453f;    // frac * ln2, in [0, ln2)
    float p = fmaf(u, 1.0f / 5040.0f, 1.0f / 720.0f);
    p = fmaf(p, u, 1.0f / 120.0f);
    p = fmaf(p, u, 1.0f / 24.0f);
    p = fmaf(p, u, 1.0f / 6.0f);
    p = fmaf(p, u, 0.5f);
    p = fmaf(p, u, 1.0f);
    p = fmaf(p, u, 1.0f);
    int ei = (int)nf;
    return p * __int_as_float((ei + 127) << 23);
}

// ---------------- T5 relative-position bias table ---------------------------
// bucket thresholds derived from floor(log(n/8)/log(16)*8), exact in f32 at the
// integer boundaries (16,32,64) and far from integers elsewhere.
__global__ void bias_init(const float* __restrict__ rel_bias) {
    int d = blockIdx.x * 256 + threadIdx.x;      // delta index 0..4095
    if (d >= 4096) return;
    int rp = d - 2048;                           // k - q
    int n = -rp;                                 // q - k
    int ret = 0;
    if (n < 0) { ret = 16; n = -n; }
    int bucket;
    if      (n <  8) bucket = n;
    else if (n < 12) bucket = 8;
    else if (n < 16) bucket = 9;
    else if (n < 23) bucket = 10;
    else if (n < 32) bucket = 11;
    else if (n < 46) bucket = 12;
    else if (n < 64) bucket = 13;
    else if (n < 91) bucket = 14;
    else             bucket = 15;
    bucket += ret;
    #pragma unroll
    for (int h = 0; h < Hq; h++)
        g_bias[h * 4096 + d] = rel_bias[bucket * Hq + h];
}

// ---------------- 4096x1024 @ 1024x1024 GEMM (64x64 tile, 4x4 micro) --------
// mode 0/1/2: Y -> g_Q/g_K/g_V in [b,h,s,dkv] layout.  mode 3: X=g_ctx, Y row-major.
__global__ __launch_bounds__(256) void gemm4096(
    const float* __restrict__ Xin, const float* __restrict__ W,
    float* __restrict__ Yrm, int mode)
{
    __shared__ float Xs[16][68];   // [k][m], transposed
    __shared__ float Ws[16][68];   // [k][n]
    const float* X = (mode == 3) ? g_ctx : Xin;
    const int m0 = blockIdx.y << 6;
    const int n0 = blockIdx.x << 6;
    const int t = threadIdx.x;
    const int tx = t & 15, ty = t >> 4;
    const int lr = t >> 2, lq = (t & 3) << 2;      // X tile load: 64 rows x 16 cols
    const int wr = t >> 4, wc = (t & 15) << 2;     // W tile load: 16 rows x 64 cols
    float acc[4][4] = {};
    for (int k0 = 0; k0 < Dq; k0 += 16) {
        float4 xv = *(const float4*)&X[(m0 + lr) * Dq + k0 + lq];
        float4 wv = *(const float4*)&W[(k0 + wr) * Dq + n0 + wc];
        __syncthreads();
        Xs[lq + 0][lr] = xv.x; Xs[lq + 1][lr] = xv.y;
        Xs[lq + 2][lr] = xv.z; Xs[lq + 3][lr] = xv.w;
        *(float4*)&Ws[wr][wc] = wv;
        __syncthreads();
        #pragma unroll
        for (int kk = 0; kk < 16; kk++) {
            float4 av = *(const float4*)&Xs[kk][ty << 2];
            float4 bv = *(const float4*)&Ws[kk][tx << 2];
            float a[4] = {av.x, av.y, av.z, av.w};
            float bb[4] = {bv.x, bv.y, bv.z, bv.w};
            #pragma unroll
            for (int r = 0; r < 4; r++)
                #pragma unroll
                for (int c = 0; c < 4; c++)
                    acc[r][c] = fmaf(a[r], bb[c], acc[r][c]);
        }
    }
    if (mode <= 2) {
        float* dst = (mode == 0) ? g_Q : (mode == 1) ? g_K : g_V;
        #pragma unroll
        for (int r = 0; r < 4; r++) {
            int m = m0 + (ty << 2) + r;
            int b = m >> 11, s = m & 2047;
            #pragma unroll
            for (int c = 0; c < 4; c++) {
                int n = n0 + (tx << 2) + c;
                int h = n >> 6, dv = n & 63;
                dst[((b * Hq + h) * Sq + s) * DKV + dv] = acc[r][c];
            }
        }
    } else {
        #pragma unroll
        for (int r = 0; r < 4; r++) {
            int m = m0 + (ty << 2) + r;
            *(float4*)&Yrm[m * Dq + n0 + (tx << 2)] =
                make_float4(acc[r][0], acc[r][1], acc[r][2], acc[r][3]);
        }
    }
}

// ---------------- scores: S = QK^T/8 + bias, mask, store raw + row sumexp ---
__global__ __launch_bounds__(256) void attn_scores(
    const int* __restrict__ mask, float* __restrict__ attn)
{
    __shared__ float Qs[64][68];   // [dkv][q]
    __shared__ float Ks[64][68];   // [dkv][k]
    __shared__ float biasW[128];   // bias window for this (q0,k0): delta-span 127
    __shared__ int   maskS[64];
    const int q0 = blockIdx.x << 6;
    const int h = blockIdx.y, b = blockIdx.z;
    const int bh = b * Hq + h;
    const int t = threadIdx.x;
    const int tx = t & 15, ty = t >> 4;

    #pragma unroll
    for (int it = 0; it < 4; it++) {             // Q tile once, transposed
        int lin = t + (it << 8);
        int row = lin >> 4;
        int c4 = (lin & 15) << 2;
        float4 v = *(const float4*)&g_Q[(bh * Sq + q0 + row) * DKV + c4];
        Qs[c4 + 0][row] = v.x; Qs[c4 + 1][row] = v.y;
        Qs[c4 + 2][row] = v.z; Qs[c4 + 3][row] = v.w;
    }
    float rsum[4] = {0.f, 0.f, 0.f, 0.f};
    for (int k0 = 0; k0 < Sq; k0 += 64) {
        __syncthreads();
        #pragma unroll
        for (int it = 0; it < 4; it++) {         // K tile, transposed
            int lin = t + (it << 8);
            int row = lin >> 4;
            int c4 = (lin & 15) << 2;
            float4 v = *(const float4*)&g_K[(bh * Sq + k0 + row) * DKV + c4];
            Ks[c4 + 0][row] = v.x; Ks[c4 + 1][row] = v.y;
            Ks[c4 + 2][row] = v.z; Ks[c4 + 3][row] = v.w;
        }
        if (t < 127) biasW[t] = g_bias[h * 4096 + (k0 - q0 + t - 63 + 2048)];
        if (t < 64)  maskS[t] = mask[b * Sq + k0 + t];
        __syncthreads();

        float acc[4][4] = {};
        #pragma unroll 8
        for (int kk = 0; kk < 64; kk++) {
            float4 av = *(const float4*)&Qs[kk][ty << 2];
            float4 bv = *(const float4*)&Ks[kk][tx << 2];
            float a[4] = {av.x, av.y, av.z, av.w};
            float bb[4] = {bv.x, bv.y, bv.z, bv.w};
            #pragma unroll
            for (int r = 0; r < 4; r++)
                #pragma unroll
                for (int c = 0; c < 4; c++)
                    acc[r][c] = fmaf(a[r], bb[c], acc[r][c]);
        }
        #pragma unroll
        for (int r = 0; r < 4; r++) {
            int qr = (ty << 2) + r;
            float vv[4];
            #pragma unroll
            for (int c = 0; c < 4; c++) {
                int kc = (tx << 2) + c;
                float sc = fmaf(acc[r][c], 0.125f, biasW[kc - qr + 63]);
                if (maskS[kc] == 0) sc = -1e9f;
                vv[c] = sc;
            }
            *(float4*)&attn[(size_t)(bh * Sq + q0 + qr) * Sq + k0 + (tx << 2)] =
                make_float4(vv[0], vv[1], vv[2], vv[3]);
            float e = fexp(vv[0]) + fexp(vv[1]) + fexp(vv[2]) + fexp(vv[3]);
            e += __shfl_xor_sync(0xffffffffu, e, 8, 16);
            e += __shfl_xor_sync(0xffffffffu, e, 4, 16);
            e += __shfl_xor_sync(0xffffffffu, e, 2, 16);
            e += __shfl_xor_sync(0xffffffffu, e, 1, 16);
            rsum[r] += e;
        }
    }
    if (tx == 0) {
        #pragma unroll
        for (int r = 0; r < 4; r++)
            g_rowsum[bh * Sq + q0 + (ty << 2) + r] = rsum[r];
    }
}

// ---------------- context: P = exp(S)/l (written in place), ctx = P @ V -----
__global__ __launch_bounds__(256) void attn_ctx(float* __restrict__ attn)
{
    __shared__ float Ps[64][68];   // [k][q]
    __shared__ float Vs[64][68];   // [k][dv]
    __shared__ float rinv[64];
    const int q0 = blockIdx.x << 6;
    const int h = blockIdx.y, b = blockIdx.z;
    const int bh = b * Hq + h;
    const int t = threadIdx.x;
    const int tx = t & 15, ty = t >> 4;
    if (t < 64) rinv[t] = 1.0f / g_rowsum[bh * Sq + q0 + t];
    float acc[4][4] = {};
    for (int k0 = 0; k0 < Sq; k0 += 64) {
        __syncthreads();
        #pragma unroll
        for (int it = 0; it < 4; it++) {
            int lin = t + (it << 8);
            int row = lin >> 4;
            int c4 = (lin & 15) << 2;
            size_t gi = (size_t)(bh * Sq + q0 + row) * Sq + k0 + c4;
            float4 v = *(const float4*)&attn[gi];
            float ri = rinv[row];
            v.x = fexp(v.x) * ri; v.y = fexp(v.y) * ri;
            v.z = fexp(v.z) * ri; v.w = fexp(v.w) * ri;
            *(float4*)&attn[gi] = v;                 // final attn_weights output
            Ps[c4 + 0][row] = v.x; Ps[c4 + 1][row] = v.y;
            Ps[c4 + 2][row] = v.z; Ps[c4 + 3][row] = v.w;
            float4 vt = *(const float4*)&g_V[(bh * Sq + k0 + row) * DKV + c4];
            *(float4*)&Vs[row][c4] = vt;
        }
        __syncthreads();
        #pragma unroll 8
        for (int kk = 0; kk < 64; kk++) {
            float4 av = *(const float4*)&Ps[kk][ty << 2];
            float4 bv = *(const float4*)&Vs[kk][tx << 2];
            float a[4] = {av.x, av.y, av.z, av.w};
            float bb[4] = {bv.x, bv.y, bv.z, bv.w};
            #pragma unroll
            for (int r = 0; r < 4; r++)
                #pragma unroll
                for (int c = 0; c < 4; c++)
                    acc[r][c] = fmaf(a[r], bb[c], acc[r][c]);
        }
    }
    #pragma unroll
    for (int r = 0; r < 4; r++) {
        int q = q0 + (ty << 2) + r;
        *(float4*)&g_ctx[(b * Sq + q) * Dq + (h << 6) + (tx << 2)] =
            make_float4(acc[r][0], acc[r][1], acc[r][2], acc[r][3]);
    }
}

// ---------------- launch --------------------------------------------------
extern "C" void kernel_launch(void* const* d_in, const int* in_sizes, int n_in,
                              void* d_out, int out_size)
{
    const float* hs   = (const float*)d_in[0];   // [2,2048,1024]
    const int*   mask = (const int*)d_in[1];     // [2,2048]
    const float* Wq   = (const float*)d_in[2];
    const float* Wk   = (const float*)d_in[3];
    const float* Wv   = (const float*)d_in[4];
    const float* Wo   = (const float*)d_in[5];
    const float* rb   = (const float*)d_in[6];   // [32,16]
    float* out  = (float*)d_out;                           // [2,2048,1024]
    float* attn = out + (size_t)Bq * Sq * Dq;              // [2,16,2048,2048]

    bias_init<<<16, 256>>>(rb);

    dim3 gp(Dq / 64, (Bq * Sq) / 64);            // (16, 64)
    gemm4096<<<gp, 256>>>(hs, Wq, nullptr, 0);
    gemm4096<<<gp, 256>>>(hs, Wk, nullptr, 1);
    gemm4096<<<gp, 256>>>(hs, Wv, nullptr, 2);

    dim3 ga(Sq / 64, Hq, Bq);                    // (32, 16, 2)
    attn_scores<<<ga, 256>>>(mask, attn);
    attn_ctx<<<ga, 256>>>(attn);

    gemm4096<<<gp, 256>>>(nullptr, Wo, out, 3);
}